// round 7
// baseline (speedup 1.0000x reference)
#include <cuda_runtime.h>
#include <cuda_bf16.h>
#include <mma.h>
#include <math.h>

using namespace nvcuda;

#define BATCH 16
#define P1H 97
#define P1W 383
#define C1 32
#define P2H 47
#define P2W 190
#define C2 64
#define FLAT 571520          // 47*190*64
#define KSLICE 640           // 893 * 640 = 571520 exactly
#define NSLICES 893
#define NCHUNK 80            // KSLICE / 8
#define WS_LD 772            // 768 + 4 pad floats per k-row
#define WS_FLOATS (8 * WS_LD)            // one stage: 6176 floats
#define XS_FLOATS (KSLICE * 20)          // 12800 floats
#define FC_SMEM_BYTES ((XS_FLOATS + 3 * WS_FLOATS) * 4)   // 125,312 B

// ---------------- scratch (device globals; allocations are forbidden) -------
__device__ __align__(128) __nv_bfloat16 g_x1b[(size_t)BATCH * P1H * P1W * C1]; // conv1 out bf16
__device__ __align__(16)  __nv_bfloat16 g_w2b[288 * 64];                       // conv2 weights bf16
__device__ __align__(16)  float g_x2[(size_t)BATCH * FLAT];                    // conv2 out [b][k]
__device__ float g_ypre[512 * 16];   // [n][b]
__device__ float g_zpre[256 * 16];
__device__ float g_y2[256 * 16];
__device__ float g_y3[2925 * 16];
__device__ float g_z4[64 * 16];
__device__ float g_z5[900 * 16];

__device__ __forceinline__ float leaky_f(float x) { return x >= 0.f ? x : 0.01f * x; }

// ---------------- prep: conv2 weight -> bf16 ; bias-init split-K accumulators
__global__ void prep_kernel(const float* __restrict__ w2,
                            const float* __restrict__ b512,
                            const float* __restrict__ b256b,
                            const float* __restrict__ bcls) {
    int i = blockIdx.x * 256 + threadIdx.x;
    if (i < 288 * 64) g_w2b[i] = __float2bfloat16(w2[i]);
    if (i < 512 * 16) g_ypre[i] = b512[i >> 4];
    if (i < 256 * 16) g_zpre[i] = b256b[i >> 4];
    if (i < 2925 * 16) g_y3[i] = bcls[i >> 4];
}

// ---------------- conv1 (3x3, 1->32) + relu + maxpool2, fused, bf16 output --
__global__ void __launch_bounds__(256) conv1_kernel(const float* __restrict__ hidden,
                                                    const float* __restrict__ w1,
                                                    const float* __restrict__ b1) {
    __shared__ float ins[4 * 768];
    __shared__ float w1s[9 * 32];
    __shared__ float b1s[32];
    int b = blockIdx.y, ph = blockIdx.x;
    int tid = threadIdx.x;

    const float* src = hidden + ((size_t)b * 197 + 2 * ph) * 768;
    for (int i = tid; i < 4 * 768; i += 256) ins[i] = src[i];
    if (tid < 288) w1s[tid] = w1[tid];
    if (tid < 32) b1s[tid] = b1[tid];
    __syncthreads();

    int cg = tid >> 6;          // 0..3 (channel group of 8)
    int pwl = tid & 63;         // 0..63
    int c0 = cg * 8;

    float wv[9][8];
#pragma unroll
    for (int t = 0; t < 9; t++)
#pragma unroll
        for (int cc = 0; cc < 8; cc++) wv[t][cc] = w1s[t * 32 + c0 + cc];

    for (int it = 0; it < 6; it++) {
        int pw = it * 64 + pwl;
        if (pw >= 383) break;
        float in[4][4];
#pragma unroll
        for (int r = 0; r < 4; r++)
#pragma unroll
            for (int c = 0; c < 4; c++) in[r][c] = ins[r * 768 + 2 * pw + c];

        float acc[2][2][8];
#pragma unroll
        for (int i = 0; i < 2; i++)
#pragma unroll
            for (int j = 0; j < 2; j++)
#pragma unroll
                for (int cc = 0; cc < 8; cc++) acc[i][j][cc] = 0.f;

#pragma unroll
        for (int t = 0; t < 9; t++) {
            int kh = t / 3, kw = t % 3;
#pragma unroll
            for (int i = 0; i < 2; i++)
#pragma unroll
                for (int j = 0; j < 2; j++) {
                    float x = in[i + kh][j + kw];
#pragma unroll
                    for (int cc = 0; cc < 8; cc++)
                        acc[i][j][cc] = fmaf(x, wv[t][cc], acc[i][j][cc]);
                }
        }

        size_t o = (((size_t)b * P1H + ph) * P1W + pw) * C1 + c0;
        __nv_bfloat162* dst = reinterpret_cast<__nv_bfloat162*>(g_x1b + o);
#pragma unroll
        for (int t = 0; t < 4; t++) {
            int cc = 2 * t;
            float m0 = fmaxf(fmaxf(acc[0][0][cc],     acc[0][1][cc]),
                             fmaxf(acc[1][0][cc],     acc[1][1][cc]));
            float m1 = fmaxf(fmaxf(acc[0][0][cc + 1], acc[0][1][cc + 1]),
                             fmaxf(acc[1][0][cc + 1], acc[1][1][cc + 1]));
            dst[t] = __floats2bfloat162_rn(fmaxf(m0 + b1s[c0 + cc], 0.f),
                                           fmaxf(m1 + b1s[c0 + cc + 1], 0.f));
        }
    }
}

// ---------------- conv2 (3x3, 32->64) bf16 wmma implicit GEMM + relu + pool --
#define CV2_BPAD 72
__global__ void __launch_bounds__(256) conv2_kernel(const float* __restrict__ b2) {
    extern __shared__ __align__(16) __nv_bfloat16 smem_h[];
    __nv_bfloat16* x1s = smem_h;                 // 6*1088 halfs = 13056 B
    __nv_bfloat16* w2s = smem_h + 6 * 1088;      // 288*72 halfs = 41472 B

    int wt = blockIdx.x;        // 0..11
    int pb = blockIdx.y;        // 0..23
    int b = blockIdx.z;         // 0..15
    int tid = threadIdx.x;
    int h0 = 4 * pb;
    int w0 = wt * 32;

    // stage A: 6 rows x 136 uint4 (border-clamped; clamped data only feeds discarded outputs)
    for (int i = tid; i < 6 * 136; i += 256) {
        int r = i / 136, q = i - r * 136;
        int row = h0 + r; if (row > 96) row = 96;
        int col = w0 + (q >> 2); if (col > 382) col = 382;
        const uint4 v = *(const uint4*)(g_x1b + (((size_t)b * P1H + row) * P1W + col) * C1 + (q & 3) * 8);
        *(uint4*)(x1s + (size_t)r * 1088 + q * 8) = v;
    }
    // stage B with row padding 64->72: 288 rows x 8 uint4 (8 halves each)
    for (int i = tid; i < 2304; i += 256) {
        int k = i >> 3, n0 = (i & 7) * 8;
        uint4 v = *(const uint4*)(g_w2b + k * 64 + n0);
        *(uint4*)(w2s + k * CV2_BPAD + n0) = v;
    }
    __syncthreads();

    int wid = tid >> 5;
    int rloc = wid >> 1;            // conv-row offset 0..3
    int wOff = (wid & 1) * 16;      // col half

    wmma::fragment<wmma::matrix_a, 16, 16, 16, __nv_bfloat16, wmma::row_major> af;
    wmma::fragment<wmma::matrix_b, 16, 16, 16, __nv_bfloat16, wmma::row_major> bf;
    wmma::fragment<wmma::accumulator, 16, 16, 16, float> acc[4];
#pragma unroll
    for (int nf = 0; nf < 4; nf++) wmma::fill_fragment(acc[nf], 0.f);

#pragma unroll
    for (int kh = 0; kh < 3; kh++) {
        const __nv_bfloat16* ap = x1s + (rloc + kh) * 1088 + wOff * 32;
#pragma unroll
        for (int jc = 0; jc < 6; jc++) {
            wmma::load_matrix_sync(af, ap + jc * 16, 32);
            const __nv_bfloat16* bp = w2s + (kh * 96 + jc * 16) * CV2_BPAD;
#pragma unroll
            for (int nf = 0; nf < 4; nf++) {
                wmma::load_matrix_sync(bf, bp + nf * 16, CV2_BPAD);
                wmma::mma_sync(acc[nf], af, bf, acc[nf]);
            }
        }
    }

    __syncthreads();                 // B fully consumed -> reuse as C (fp32)
    float* cs = reinterpret_cast<float*>(w2s);   // 8 x 1024 floats = 32 KB
#pragma unroll
    for (int nf = 0; nf < 4; nf++)
        wmma::store_matrix_sync(cs + wid * 1024 + nf * 16, acc[nf], 64, wmma::mem_row_major);
    __syncthreads();

    // pooling epilogue: tid -> (pr 0..1, pj 0..15, 8 channels)
    int pr = tid >> 7;
    int pj = (tid >> 3) & 15;
    int c0 = (tid & 7) * 8;
    int ph2 = 2 * pb + pr;
    int pwg = wt * 16 + pj;
    if (ph2 < P2H && pwg < P2W) {
        float v[8];
#pragma unroll
        for (int cc = 0; cc < 8; cc++) {
            int c = c0 + cc;
            float m = -1e30f;
#pragma unroll
            for (int i = 0; i < 2; i++)
#pragma unroll
                for (int j = 0; j < 2; j++) {
                    int rr = 2 * pr + i;
                    int jj = 2 * pj + j;
                    m = fmaxf(m, cs[(rr * 2 + (jj >> 4)) * 1024 + (jj & 15) * 64 + c]);
                }
            v[cc] = fmaxf(m + b2[c], 0.f);
        }
        size_t o = (size_t)b * FLAT + ((size_t)ph2 * P2W + pwg) * C2 + c0;
        float4 o0 = {v[0], v[1], v[2], v[3]};
        float4 o1 = {v[4], v[5], v[6], v[7]};
        *reinterpret_cast<float4*>(g_x2 + o) = o0;
        *reinterpret_cast<float4*>(g_x2 + o + 4) = o1;
    }
}

// ---------------- big FC via TF32 tensor cores + cp.async ring ---------------
// D[16, 768] += x[16, K] @ (w512 | w256b), split-K over 893 slices.
// 512 thr / 16 warps; warp owns 48 cols (3 n16 tiles). Weight chunks
// (8 k-rows x 768 cols fp32 = 24KB) stream via 3-stage cp.async.cg ring.
// fp32 bits fed to tf32 MMA directly (HW truncation; within error budget).
__global__ void __launch_bounds__(512) fcbig_tf32_kernel(const float* __restrict__ w512,
                                                         const float* __restrict__ w256b) {
    extern __shared__ __align__(16) float smem_f[];
    float* xs = smem_f;                          // [KSLICE][20] x^T
    float* ws = smem_f + XS_FLOATS;              // 3 stages x [8][WS_LD]

    int tid = threadIdx.x;
    int wid = tid >> 5;
    int lane = tid & 31;
    size_t k0 = (size_t)blockIdx.x * KSLICE;

    // stage x^T slice [k][b] (coalesced gmem reads per batch row)
    for (int b = 0; b < 16; b++) {
        const float* src = g_x2 + (size_t)b * FLAT + k0;
        for (int kl = tid; kl < KSLICE; kl += 512)
            xs[kl * 20 + b] = src[kl];
    }

    // per-thread cp.async source/dest precompute: 3 x 16B per thread per chunk
    const float* gsrc[3];
    int gstep[3];
    unsigned soff[3];
#pragma unroll
    for (int i = 0; i < 3; i++) {
        int idx = tid + i * 512;              // 0..1535 over [8 rows][192 float4]
        int r = idx / 192;
        int c4 = idx - r * 192;
        if (c4 < 128) { gsrc[i] = w512  + (k0 + r) * 512 + c4 * 4;         gstep[i] = 8 * 512; }
        else          { gsrc[i] = w256b + (k0 + r) * 256 + (c4 - 128) * 4; gstep[i] = 8 * 256; }
        soff[i] = (unsigned)((r * WS_LD + c4 * 4) * 4);
    }
    unsigned ws_base = (unsigned)__cvta_generic_to_shared(ws);

#define FC_ISSUE(c)                                                               \
    {                                                                             \
        unsigned sb = ws_base + ((c) % 3) * (WS_FLOATS * 4);                      \
        _Pragma("unroll")                                                         \
        for (int i = 0; i < 3; i++) {                                             \
            const float* g = gsrc[i] + (size_t)(c) * gstep[i];                    \
            asm volatile("cp.async.cg.shared.global [%0], [%1], 16;"              \
                         :: "r"(sb + soff[i]), "l"(g));                           \
        }                                                                         \
    }

    FC_ISSUE(0);
    asm volatile("cp.async.commit_group;");
    FC_ISSUE(1);
    asm volatile("cp.async.commit_group;");

    wmma::fragment<wmma::matrix_a, 16, 16, 8, wmma::precision::tf32, wmma::col_major> af;
    wmma::fragment<wmma::matrix_b, 16, 16, 8, wmma::precision::tf32, wmma::row_major> bfr;
    wmma::fragment<wmma::accumulator, 16, 16, 8, float> acc[3];
#pragma unroll
    for (int t = 0; t < 3; t++) wmma::fill_fragment(acc[t], 0.f);

    for (int c = 0; c < NCHUNK; c++) {
        asm volatile("cp.async.wait_group 1;");
        __syncthreads();                         // chunk c visible to all warps

        const float* buf = ws + (c % 3) * WS_FLOATS;
        wmma::load_matrix_sync(af, xs + c * 160, 20);    // 8 k-rows of x^T
        const float* wb = buf + wid * 48;
#pragma unroll
        for (int t = 0; t < 3; t++) {
            wmma::load_matrix_sync(bfr, wb + t * 16, WS_LD);
            wmma::mma_sync(acc[t], af, bfr, acc[t]);
        }

        if (c + 2 < NCHUNK) FC_ISSUE(c + 2);
        asm volatile("cp.async.commit_group;");  // empty groups at tail keep counts aligned
    }
    __syncthreads();

    // epilogue: frag -> smem patch -> atomicAdd into bias-initialized buffers
    float* patch = ws + wid * 256;     // 16x16 row-major (m=batch, n=col)
#pragma unroll
    for (int t = 0; t < 3; t++) {
        wmma::store_matrix_sync(patch, acc[t], 16, wmma::mem_row_major);
        __syncwarp();
        int gcb = wid * 48 + t * 16;
#pragma unroll
        for (int u = 0; u < 8; u++) {
            int e = lane + u * 32;
            int m = e >> 4, n = e & 15;
            int gcol = gcb + n;
            float val = patch[e];
            float* dst = (gcol < 512) ? (g_ypre + gcol * 16 + m)
                                      : (g_zpre + (gcol - 512) * 16 + m);
            atomicAdd(dst, val);
        }
        __syncwarp();
    }
#undef FC_ISSUE
}

// ---------------- small FC: outPre[n2][b] = bias[n2] + sum_k leaky(inPre[k][b]) w[k][n2]
template <int K>
__global__ void __launch_bounds__(128) smallfc_kernel(const float* __restrict__ inPre,
                                                      const float* __restrict__ w,
                                                      const float* __restrict__ bias,
                                                      float* __restrict__ outPre,
                                                      int N2) {
    __shared__ float xs[K * 16];
    int tid = threadIdx.x;
    for (int idx = tid; idx < K * 16; idx += 128) xs[idx] = leaky_f(inPre[idx]);
    __syncthreads();

    int n2 = blockIdx.x * 128 + tid;
    if (n2 < N2) {
        float acc[16];
#pragma unroll
        for (int b = 0; b < 16; b++) acc[b] = 0.f;
#pragma unroll 8
        for (int k = 0; k < K; k++) {
            float wv = __ldg(w + (size_t)k * N2 + n2);
#pragma unroll
            for (int b = 0; b < 16; b++) acc[b] = fmaf(wv, xs[k * 16 + b], acc[b]);
        }
        float bb = bias[n2];
#pragma unroll
        for (int b = 0; b < 16; b++) outPre[n2 * 16 + b] = acc[b] + bb;
    }
}

// ---------------- split-K small FC (K=256 in 2 halves), out pre-initialized with bias
__global__ void __launch_bounds__(128) splitfc_kernel(const float* __restrict__ inPre,
                                                      const float* __restrict__ w,
                                                      float* __restrict__ outAcc,
                                                      int N2) {
    __shared__ float xs[128 * 16];
    int tid = threadIdx.x;
    int kh = blockIdx.y;                    // 0..1 -> k in [kh*128, kh*128+128)
    const float* ip = inPre + kh * 128 * 16;
    for (int idx = tid; idx < 128 * 16; idx += 128) xs[idx] = leaky_f(ip[idx]);
    __syncthreads();

    int n2 = blockIdx.x * 128 + tid;
    if (n2 < N2) {
        float acc[16];
#pragma unroll
        for (int b = 0; b < 16; b++) acc[b] = 0.f;
        const float* wp = w + (size_t)kh * 128 * N2 + n2;
#pragma unroll 8
        for (int k = 0; k < 128; k++) {
            float wv = __ldg(wp + (size_t)k * N2);
#pragma unroll
            for (int b = 0; b < 16; b++) acc[b] = fmaf(wv, xs[k * 16 + b], acc[b]);
        }
#pragma unroll
        for (int b = 0; b < 16; b++) atomicAdd(outAcc + n2 * 16 + b, acc[b]);
    }
}

// ---------------- fused z-chain: 256 ->128 ->128 ->64, one CTA ---------------
__global__ void __launch_bounds__(128) zfused_kernel(const float* __restrict__ w128a,
                                                     const float* __restrict__ b128a,
                                                     const float* __restrict__ w128b,
                                                     const float* __restrict__ b128b,
                                                     const float* __restrict__ w64,
                                                     const float* __restrict__ b64) {
    __shared__ float xa[256 * 16];
    __shared__ float xb[128 * 16];
    int tid = threadIdx.x;
    for (int idx = tid; idx < 256 * 16; idx += 128) xa[idx] = leaky_f(g_zpre[idx]);
    __syncthreads();

    {
        float acc[16];
#pragma unroll
        for (int b = 0; b < 16; b++) acc[b] = 0.f;
#pragma unroll 8
        for (int k = 0; k < 256; k++) {
            float wv = __ldg(w128a + (size_t)k * 128 + tid);
#pragma unroll
            for (int b = 0; b < 16; b++) acc[b] = fmaf(wv, xa[k * 16 + b], acc[b]);
        }
        float bb = b128a[tid];
#pragma unroll
        for (int b = 0; b < 16; b++) xb[tid * 16 + b] = leaky_f(acc[b] + bb);
    }
    __syncthreads();

    {
        float acc[16];
#pragma unroll
        for (int b = 0; b < 16; b++) acc[b] = 0.f;
#pragma unroll 8
        for (int k = 0; k < 128; k++) {
            float wv = __ldg(w128b + (size_t)k * 128 + tid);
#pragma unroll
            for (int b = 0; b < 16; b++) acc[b] = fmaf(wv, xb[k * 16 + b], acc[b]);
        }
        float bb = b128b[tid];
#pragma unroll
        for (int b = 0; b < 16; b++) xa[tid * 16 + b] = leaky_f(acc[b] + bb);
    }
    __syncthreads();

    if (tid < 64) {
        float acc[16];
#pragma unroll
        for (int b = 0; b < 16; b++) acc[b] = 0.f;
#pragma unroll 8
        for (int k = 0; k < 128; k++) {
            float wv = __ldg(w64 + (size_t)k * 64 + tid);
#pragma unroll
            for (int b = 0; b < 16; b++) acc[b] = fmaf(wv, xa[k * 16 + b], acc[b]);
        }
        float bb = b64[tid];
#pragma unroll
        for (int b = 0; b < 16; b++) g_z4[tid * 16 + b] = acc[b] + bb;
    }
}

// ---------------- heads: softmax(leaky(y3)@wsm+bsm), sigmoid(leaky(z5)@wsig+bsig)
__global__ void heads_kernel(const float* __restrict__ wsm, const float* __restrict__ bsm,
                             const float* __restrict__ wsig, const float* __restrict__ bsig,
                             float* __restrict__ out) {
    int idx = blockIdx.x * 256 + threadIdx.x;
    if (idx < 3600) {
        int b = idx / 225, p = idx % 225;
        float yv[13];
#pragma unroll
        for (int i = 0; i < 13; i++) yv[i] = leaky_f(g_y3[(p * 13 + i) * 16 + b]);
        float l[13];
        float m = -1e30f;
#pragma unroll
        for (int o = 0; o < 13; o++) {
            float s = bsm[o];
#pragma unroll
            for (int i = 0; i < 13; i++) s = fmaf(yv[i], wsm[i * 13 + o], s);
            l[o] = s;
            m = fmaxf(m, s);
        }
        float sum = 0.f;
#pragma unroll
        for (int o = 0; o < 13; o++) { l[o] = expf(l[o] - m); sum += l[o]; }
        float inv = 1.f / sum;
        float* dst = out + (size_t)(b * 225 + p) * 13;
#pragma unroll
        for (int o = 0; o < 13; o++) dst[o] = l[o] * inv;
    } else if (idx < 7200) {
        int j = idx - 3600;
        int b = j / 225, p = j % 225;
        float zv[4];
#pragma unroll
        for (int i = 0; i < 4; i++) zv[i] = leaky_f(g_z5[(p * 4 + i) * 16 + b]);
        float* dst = out + 46800 + (size_t)(b * 225 + p) * 4;
#pragma unroll
        for (int o = 0; o < 4; o++) {
            float s = bsig[o];
#pragma unroll
            for (int i = 0; i < 4; i++) s = fmaf(zv[i], wsig[i * 4 + o], s);
            dst[o] = 1.f / (1.f + expf(-s));
        }
    }
}

// ---------------- launch ----------------------------------------------------
extern "C" void kernel_launch(void* const* d_in, const int* in_sizes, int n_in,
                              void* d_out, int out_size) {
    const float* hidden  = (const float*)d_in[0];
    const float* conv1_w = (const float*)d_in[1];
    const float* conv1_b = (const float*)d_in[2];
    const float* conv2_w = (const float*)d_in[3];
    const float* conv2_b = (const float*)d_in[4];
    const float* w512    = (const float*)d_in[5];
    const float* b512    = (const float*)d_in[6];
    const float* w256a   = (const float*)d_in[7];
    const float* b256a   = (const float*)d_in[8];
    const float* wcls    = (const float*)d_in[9];
    const float* bcls    = (const float*)d_in[10];
    const float* wsm     = (const float*)d_in[11];
    const float* bsm     = (const float*)d_in[12];
    const float* w256b   = (const float*)d_in[13];
    const float* b256b   = (const float*)d_in[14];
    const float* w128a   = (const float*)d_in[15];
    const float* b128a   = (const float*)d_in[16];
    const float* w128b   = (const float*)d_in[17];
    const float* b128b   = (const float*)d_in[18];
    const float* w64     = (const float*)d_in[19];
    const float* b64     = (const float*)d_in[20];
    const float* wreg    = (const float*)d_in[21];
    const float* breg    = (const float*)d_in[22];
    const float* wsig    = (const float*)d_in[23];
    const float* bsig    = (const float*)d_in[24];
    float* out = (float*)d_out;

    float *ypre, *y2, *y3, *z4, *z5;
    cudaGetSymbolAddress((void**)&ypre, g_ypre);
    cudaGetSymbolAddress((void**)&y2, g_y2);
    cudaGetSymbolAddress((void**)&y3, g_y3);
    cudaGetSymbolAddress((void**)&z4, g_z4);
    cudaGetSymbolAddress((void**)&z5, g_z5);

    static bool attr_set = false;
    if (!attr_set) {
        cudaFuncSetAttribute(conv2_kernel, cudaFuncAttributeMaxDynamicSharedMemorySize, 54528);
        cudaFuncSetAttribute(fcbig_tf32_kernel, cudaFuncAttributeMaxDynamicSharedMemorySize, FC_SMEM_BYTES);
        attr_set = true;
    }

    prep_kernel<<<183, 256>>>(conv2_w, b512, b256b, bcls);
    conv1_kernel<<<dim3(P1H, BATCH), 256>>>(hidden, conv1_w, conv1_b);
    conv2_kernel<<<dim3(12, 24, BATCH), 256, 54528>>>(conv2_b);
    fcbig_tf32_kernel<<<NSLICES, 512, FC_SMEM_BYTES>>>(w512, w256b);

    smallfc_kernel<512><<<2, 128>>>(ypre, w256a, b256a, y2, 256);
    splitfc_kernel<<<dim3(23, 2), 128>>>(y2, wcls, y3, 2925);
    zfused_kernel<<<1, 128>>>(w128a, b128a, w128b, b128b, w64, b64);
    smallfc_kernel<64><<<8, 128>>>(z4, wreg, breg, z5, 900);

    heads_kernel<<<29, 256>>>(wsm, bsm, wsig, bsig, out);
}

// round 8
// speedup vs baseline: 1.1250x; 1.1250x over previous
#include <cuda_runtime.h>
#include <cuda_bf16.h>
#include <mma.h>
#include <math.h>

using namespace nvcuda;

#define BATCH 16
#define P1H 97
#define P1W 383
#define C1 32
#define P2H 47
#define P2W 190
#define C2 64
#define FLAT 571520          // 47*190*64
#define KSLICE 640           // 893 * 640 = 571520 exactly
#define NSLICES 893
#define NCHUNK 80            // KSLICE / 8
#define FC_STAGES 5
#define FC_WLD 52                               // 48 cols + 4 pad floats per k-row
#define FC_STAGE_FLOATS (8 * FC_WLD)            // 416 floats per stage
#define FC_WARP_FLOATS (FC_STAGES * FC_STAGE_FLOATS)   // 2080
#define XS_FLOATS (KSLICE * 20)                 // 12800
#define FC_SMEM_BYTES ((XS_FLOATS + 16 * FC_WARP_FLOATS) * 4)   // 184,320 B

// ---------------- scratch (device globals; allocations are forbidden) -------
__device__ __align__(128) __nv_bfloat16 g_x1b[(size_t)BATCH * P1H * P1W * C1]; // conv1 out bf16
__device__ __align__(16)  __nv_bfloat16 g_w2b[288 * 64];                       // conv2 weights bf16
__device__ __align__(16)  float g_x2[(size_t)BATCH * FLAT];                    // conv2 out [b][k]
__device__ float g_ypre[512 * 16];   // [n][b]
__device__ float g_zpre[256 * 16];
__device__ float g_y2[256 * 16];
__device__ float g_y3[2925 * 16];
__device__ float g_z4[64 * 16];
__device__ float g_z5[900 * 16];

__device__ __forceinline__ float leaky_f(float x) { return x >= 0.f ? x : 0.01f * x; }

// ---------------- prep: conv2 weight -> bf16 ; bias-init split-K accumulators
__global__ void prep_kernel(const float* __restrict__ w2,
                            const float* __restrict__ b512,
                            const float* __restrict__ b256b,
                            const float* __restrict__ bcls,
                            const float* __restrict__ b256a) {
    int i = blockIdx.x * 256 + threadIdx.x;
    if (i < 288 * 64) g_w2b[i] = __float2bfloat16(w2[i]);
    if (i < 512 * 16) g_ypre[i] = b512[i >> 4];
    if (i < 256 * 16) g_zpre[i] = b256b[i >> 4];
    if (i < 256 * 16) g_y2[i] = b256a[i >> 4];
    if (i < 2925 * 16) g_y3[i] = bcls[i >> 4];
}

// ---------------- conv1 (3x3, 1->32) + relu + maxpool2, fused, bf16 output --
__global__ void __launch_bounds__(256) conv1_kernel(const float* __restrict__ hidden,
                                                    const float* __restrict__ w1,
                                                    const float* __restrict__ b1) {
    __shared__ float ins[4 * 768];
    __shared__ float w1s[9 * 32];
    __shared__ float b1s[32];
    int b = blockIdx.y, ph = blockIdx.x;
    int tid = threadIdx.x;

    const float* src = hidden + ((size_t)b * 197 + 2 * ph) * 768;
    for (int i = tid; i < 4 * 768; i += 256) ins[i] = src[i];
    if (tid < 288) w1s[tid] = w1[tid];
    if (tid < 32) b1s[tid] = b1[tid];
    __syncthreads();

    int cg = tid >> 6;          // 0..3 (channel group of 8)
    int pwl = tid & 63;         // 0..63
    int c0 = cg * 8;

    float wv[9][8];
#pragma unroll
    for (int t = 0; t < 9; t++)
#pragma unroll
        for (int cc = 0; cc < 8; cc++) wv[t][cc] = w1s[t * 32 + c0 + cc];

    for (int it = 0; it < 6; it++) {
        int pw = it * 64 + pwl;
        if (pw >= 383) break;
        float in[4][4];
#pragma unroll
        for (int r = 0; r < 4; r++)
#pragma unroll
            for (int c = 0; c < 4; c++) in[r][c] = ins[r * 768 + 2 * pw + c];

        float acc[2][2][8];
#pragma unroll
        for (int i = 0; i < 2; i++)
#pragma unroll
            for (int j = 0; j < 2; j++)
#pragma unroll
                for (int cc = 0; cc < 8; cc++) acc[i][j][cc] = 0.f;

#pragma unroll
        for (int t = 0; t < 9; t++) {
            int kh = t / 3, kw = t % 3;
#pragma unroll
            for (int i = 0; i < 2; i++)
#pragma unroll
                for (int j = 0; j < 2; j++) {
                    float x = in[i + kh][j + kw];
#pragma unroll
                    for (int cc = 0; cc < 8; cc++)
                        acc[i][j][cc] = fmaf(x, wv[t][cc], acc[i][j][cc]);
                }
        }

        size_t o = (((size_t)b * P1H + ph) * P1W + pw) * C1 + c0;
        __nv_bfloat162* dst = reinterpret_cast<__nv_bfloat162*>(g_x1b + o);
#pragma unroll
        for (int t = 0; t < 4; t++) {
            int cc = 2 * t;
            float m0 = fmaxf(fmaxf(acc[0][0][cc],     acc[0][1][cc]),
                             fmaxf(acc[1][0][cc],     acc[1][1][cc]));
            float m1 = fmaxf(fmaxf(acc[0][0][cc + 1], acc[0][1][cc + 1]),
                             fmaxf(acc[1][0][cc + 1], acc[1][1][cc + 1]));
            dst[t] = __floats2bfloat162_rn(fmaxf(m0 + b1s[c0 + cc], 0.f),
                                           fmaxf(m1 + b1s[c0 + cc + 1], 0.f));
        }
    }
}

// ---------------- conv2 (3x3, 32->64) bf16 wmma implicit GEMM + relu + pool --
#define CV2_BPAD 72
__global__ void __launch_bounds__(256) conv2_kernel(const float* __restrict__ b2) {
    extern __shared__ __align__(16) __nv_bfloat16 smem_h[];
    __nv_bfloat16* x1s = smem_h;                 // 6*1088 halfs = 13056 B
    __nv_bfloat16* w2s = smem_h + 6 * 1088;      // 288*72 halfs = 41472 B

    int wt = blockIdx.x;        // 0..11
    int pb = blockIdx.y;        // 0..23
    int b = blockIdx.z;         // 0..15
    int tid = threadIdx.x;
    int h0 = 4 * pb;
    int w0 = wt * 32;

    // stage A: 6 rows x 136 uint4 (border-clamped; clamped data only feeds discarded outputs)
    for (int i = tid; i < 6 * 136; i += 256) {
        int r = i / 136, q = i - r * 136;
        int row = h0 + r; if (row > 96) row = 96;
        int col = w0 + (q >> 2); if (col > 382) col = 382;
        const uint4 v = *(const uint4*)(g_x1b + (((size_t)b * P1H + row) * P1W + col) * C1 + (q & 3) * 8);
        *(uint4*)(x1s + (size_t)r * 1088 + q * 8) = v;
    }
    // stage B with row padding 64->72: 288 rows x 8 uint4 (8 halves each)
    for (int i = tid; i < 2304; i += 256) {
        int k = i >> 3, n0 = (i & 7) * 8;
        uint4 v = *(const uint4*)(g_w2b + k * 64 + n0);
        *(uint4*)(w2s + k * CV2_BPAD + n0) = v;
    }
    __syncthreads();

    int wid = tid >> 5;
    int rloc = wid >> 1;            // conv-row offset 0..3
    int wOff = (wid & 1) * 16;      // col half

    wmma::fragment<wmma::matrix_a, 16, 16, 16, __nv_bfloat16, wmma::row_major> af;
    wmma::fragment<wmma::matrix_b, 16, 16, 16, __nv_bfloat16, wmma::row_major> bf;
    wmma::fragment<wmma::accumulator, 16, 16, 16, float> acc[4];
#pragma unroll
    for (int nf = 0; nf < 4; nf++) wmma::fill_fragment(acc[nf], 0.f);

#pragma unroll
    for (int kh = 0; kh < 3; kh++) {
        const __nv_bfloat16* ap = x1s + (rloc + kh) * 1088 + wOff * 32;
#pragma unroll
        for (int jc = 0; jc < 6; jc++) {
            wmma::load_matrix_sync(af, ap + jc * 16, 32);
            const __nv_bfloat16* bp = w2s + (kh * 96 + jc * 16) * CV2_BPAD;
#pragma unroll
            for (int nf = 0; nf < 4; nf++) {
                wmma::load_matrix_sync(bf, bp + nf * 16, CV2_BPAD);
                wmma::mma_sync(acc[nf], af, bf, acc[nf]);
            }
        }
    }

    __syncthreads();                 // B fully consumed -> reuse as C (fp32)
    float* cs = reinterpret_cast<float*>(w2s);   // 8 x 1024 floats = 32 KB
#pragma unroll
    for (int nf = 0; nf < 4; nf++)
        wmma::store_matrix_sync(cs + wid * 1024 + nf * 16, acc[nf], 64, wmma::mem_row_major);
    __syncthreads();

    // pooling epilogue: tid -> (pr 0..1, pj 0..15, 8 channels)
    int pr = tid >> 7;
    int pj = (tid >> 3) & 15;
    int c0 = (tid & 7) * 8;
    int ph2 = 2 * pb + pr;
    int pwg = wt * 16 + pj;
    if (ph2 < P2H && pwg < P2W) {
        float v[8];
#pragma unroll
        for (int cc = 0; cc < 8; cc++) {
            int c = c0 + cc;
            float m = -1e30f;
#pragma unroll
            for (int i = 0; i < 2; i++)
#pragma unroll
                for (int j = 0; j < 2; j++) {
                    int rr = 2 * pr + i;
                    int jj = 2 * pj + j;
                    m = fmaxf(m, cs[(rr * 2 + (jj >> 4)) * 1024 + (jj & 15) * 64 + c]);
                }
            v[cc] = fmaxf(m + b2[c], 0.f);
        }
        size_t o = (size_t)b * FLAT + ((size_t)ph2 * P2W + pwg) * C2 + c0;
        float4 o0 = {v[0], v[1], v[2], v[3]};
        float4 o1 = {v[4], v[5], v[6], v[7]};
        *reinterpret_cast<float4*>(g_x2 + o) = o0;
        *reinterpret_cast<float4*>(g_x2 + o + 4) = o1;
    }
}

// ---------------- big FC via TF32 tensor cores, warp-private cp.async rings --
// D[16, 768] += x[16, K] @ (w512 | w256b), split-K over 893 slices.
// 512 thr / 16 warps. Warp w owns cols [48w, 48w+48): its threads cp.async ONLY
// that strip into a private 5-stage ring, so the mainloop needs NO CTA barrier:
// cp.async groups are per-thread; wait_group+__syncwarp is a warp-local handoff.
__global__ void __launch_bounds__(512) fcbig_tf32_kernel(const float* __restrict__ w512,
                                                         const float* __restrict__ w256b) {
    extern __shared__ __align__(16) float smem_f[];
    float* xs = smem_f;                          // [KSLICE][20] x^T
    float* ws = smem_f + XS_FLOATS;              // [16 warps][5 stages][8][FC_WLD]

    int tid = threadIdx.x;
    int wid = tid >> 5;
    int lane = tid & 31;
    size_t k0 = (size_t)blockIdx.x * KSLICE;

    // per-thread cp.async precompute: 3 x 16B per chunk over [8 rows][12 float4]
    const float* gsrc[3];
    int gstep[3];
    unsigned soff[3];
#pragma unroll
    for (int i = 0; i < 3; i++) {
        int idx = lane + i * 32;              // 0..95
        int r = idx / 12;
        int c4 = idx - r * 12;
        int gcol = wid * 48 + c4 * 4;
        if (gcol < 512) { gsrc[i] = w512  + (k0 + r) * 512 + gcol;         gstep[i] = 8 * 512; }
        else            { gsrc[i] = w256b + (k0 + r) * 256 + (gcol - 512); gstep[i] = 8 * 256; }
        soff[i] = (unsigned)((r * FC_WLD + c4 * 4) * 4);
    }
    unsigned wbase = (unsigned)__cvta_generic_to_shared(ws) + wid * (FC_WARP_FLOATS * 4);

#define FC_ISSUE(c)                                                               \
    {                                                                             \
        unsigned sb = wbase + ((c) % FC_STAGES) * (FC_STAGE_FLOATS * 4);          \
        _Pragma("unroll")                                                         \
        for (int i = 0; i < 3; i++) {                                             \
            const float* g = gsrc[i] + (size_t)(c) * gstep[i];                    \
            asm volatile("cp.async.cg.shared.global [%0], [%1], 16;"              \
                         :: "r"(sb + soff[i]), "l"(g));                           \
        }                                                                         \
        asm volatile("cp.async.commit_group;");                                   \
    }

    // prime 4 chunks, then stage xs (overlaps first loads' latency)
    FC_ISSUE(0); FC_ISSUE(1); FC_ISSUE(2); FC_ISSUE(3);

    for (int b = 0; b < 16; b++) {
        const float* src = g_x2 + (size_t)b * FLAT + k0;
        for (int kl = tid; kl < KSLICE; kl += 512)
            xs[kl * 20 + b] = src[kl];
    }
    __syncthreads();   // xs visible to all warps; the only CTA barrier

    wmma::fragment<wmma::matrix_a, 16, 16, 8, wmma::precision::tf32, wmma::col_major> af;
    wmma::fragment<wmma::matrix_b, 16, 16, 8, wmma::precision::tf32, wmma::row_major> bfr;
    wmma::fragment<wmma::accumulator, 16, 16, 8, float> acc[3];
#pragma unroll
    for (int t = 0; t < 3; t++) wmma::fill_fragment(acc[t], 0.f);

    const float* wsw = ws + wid * FC_WARP_FLOATS;
    for (int c = 0; c < NCHUNK; c++) {
        asm volatile("cp.async.wait_group 3;");
        __syncwarp();                            // warp-local visibility of chunk c

        const float* buf = wsw + (c % FC_STAGES) * FC_STAGE_FLOATS;
        wmma::load_matrix_sync(af, xs + c * 160, 20);    // 8 k-rows of x^T
#pragma unroll
        for (int t = 0; t < 3; t++) {
            wmma::load_matrix_sync(bfr, buf + t * 16, FC_WLD);
            wmma::mma_sync(acc[t], af, bfr, acc[t]);
        }

        if (c + 4 < NCHUNK) FC_ISSUE(c + 4);
    }
    asm volatile("cp.async.wait_group 0;");
    __syncwarp();

    // epilogue (barrier-free): each warp reuses its own ring as the patch buffer
    float* patch = ws + wid * FC_WARP_FLOATS;    // 256 floats needed, 2080 available
#pragma unroll
    for (int t = 0; t < 3; t++) {
        wmma::store_matrix_sync(patch, acc[t], 16, wmma::mem_row_major);
        __syncwarp();
        int gcb = wid * 48 + t * 16;
#pragma unroll
        for (int u = 0; u < 8; u++) {
            int e = lane + u * 32;
            int m = e >> 4, n = e & 15;
            int gcol = gcb + n;
            float val = patch[e];
            float* dst = (gcol < 512) ? (g_ypre + gcol * 16 + m)
                                      : (g_zpre + (gcol - 512) * 16 + m);
            atomicAdd(dst, val);
        }
        __syncwarp();
    }
#undef FC_ISSUE
}

// ---------------- small FC: outPre[n2][b] = bias[n2] + sum_k leaky(inPre[k][b]) w[k][n2]
template <int K>
__global__ void __launch_bounds__(128) smallfc_kernel(const float* __restrict__ inPre,
                                                      const float* __restrict__ w,
                                                      const float* __restrict__ bias,
                                                      float* __restrict__ outPre,
                                                      int N2) {
    __shared__ float xs[K * 16];
    int tid = threadIdx.x;
    for (int idx = tid; idx < K * 16; idx += 128) xs[idx] = leaky_f(inPre[idx]);
    __syncthreads();

    int n2 = blockIdx.x * 128 + tid;
    if (n2 < N2) {
        float acc[16];
#pragma unroll
        for (int b = 0; b < 16; b++) acc[b] = 0.f;
#pragma unroll 8
        for (int k = 0; k < K; k++) {
            float wv = __ldg(w + (size_t)k * N2 + n2);
#pragma unroll
            for (int b = 0; b < 16; b++) acc[b] = fmaf(wv, xs[k * 16 + b], acc[b]);
        }
        float bb = bias[n2];
#pragma unroll
        for (int b = 0; b < 16; b++) outPre[n2 * 16 + b] = acc[b] + bb;
    }
}

// ---------------- split-K small FC (128-row K slices), out pre-initialized with bias
__global__ void __launch_bounds__(128) splitfc_kernel(const float* __restrict__ inPre,
                                                      const float* __restrict__ w,
                                                      float* __restrict__ outAcc,
                                                      int N2) {
    __shared__ float xs[128 * 16];
    int tid = threadIdx.x;
    int kh = blockIdx.y;                    // k in [kh*128, kh*128+128)
    const float* ip = inPre + kh * 128 * 16;
    for (int idx = tid; idx < 128 * 16; idx += 128) xs[idx] = leaky_f(ip[idx]);
    __syncthreads();

    int n2 = blockIdx.x * 128 + tid;
    if (n2 < N2) {
        float acc[16];
#pragma unroll
        for (int b = 0; b < 16; b++) acc[b] = 0.f;
        const float* wp = w + (size_t)kh * 128 * N2 + n2;
#pragma unroll 8
        for (int k = 0; k < 128; k++) {
            float wv = __ldg(wp + (size_t)k * N2);
#pragma unroll
            for (int b = 0; b < 16; b++) acc[b] = fmaf(wv, xs[k * 16 + b], acc[b]);
        }
#pragma unroll
        for (int b = 0; b < 16; b++) atomicAdd(outAcc + n2 * 16 + b, acc[b]);
    }
}

// ---------------- fused z-chain: 256 ->128 ->128 ->64, one CTA ---------------
__global__ void __launch_bounds__(128) zfused_kernel(const float* __restrict__ w128a,
                                                     const float* __restrict__ b128a,
                                                     const float* __restrict__ w128b,
                                                     const float* __restrict__ b128b,
                                                     const float* __restrict__ w64,
                                                     const float* __restrict__ b64) {
    __shared__ float xa[256 * 16];
    __shared__ float xb[128 * 16];
    int tid = threadIdx.x;
    for (int idx = tid; idx < 256 * 16; idx += 128) xa[idx] = leaky_f(g_zpre[idx]);
    __syncthreads();

    {
        float acc[16];
#pragma unroll
        for (int b = 0; b < 16; b++) acc[b] = 0.f;
#pragma unroll 8
        for (int k = 0; k < 256; k++) {
            float wv = __ldg(w128a + (size_t)k * 128 + tid);
#pragma unroll
            for (int b = 0; b < 16; b++) acc[b] = fmaf(wv, xa[k * 16 + b], acc[b]);
        }
        float bb = b128a[tid];
#pragma unroll
        for (int b = 0; b < 16; b++) xb[tid * 16 + b] = leaky_f(acc[b] + bb);
    }
    __syncthreads();

    {
        float acc[16];
#pragma unroll
        for (int b = 0; b < 16; b++) acc[b] = 0.f;
#pragma unroll 8
        for (int k = 0; k < 128; k++) {
            float wv = __ldg(w128b + (size_t)k * 128 + tid);
#pragma unroll
            for (int b = 0; b < 16; b++) acc[b] = fmaf(wv, xb[k * 16 + b], acc[b]);
        }
        float bb = b128b[tid];
#pragma unroll
        for (int b = 0; b < 16; b++) xa[tid * 16 + b] = leaky_f(acc[b] + bb);
    }
    __syncthreads();

    if (tid < 64) {
        float acc[16];
#pragma unroll
        for (int b = 0; b < 16; b++) acc[b] = 0.f;
#pragma unroll 8
        for (int k = 0; k < 128; k++) {
            float wv = __ldg(w64 + (size_t)k * 64 + tid);
#pragma unroll
            for (int b = 0; b < 16; b++) acc[b] = fmaf(wv, xa[k * 16 + b], acc[b]);
        }
        float bb = b64[tid];
#pragma unroll
        for (int b = 0; b < 16; b++) g_z4[tid * 16 + b] = acc[b] + bb;
    }
}

// ---------------- heads: softmax(leaky(y3)@wsm+bsm), sigmoid(leaky(z5)@wsig+bsig)
__global__ void heads_kernel(const float* __restrict__ wsm, const float* __restrict__ bsm,
                             const float* __restrict__ wsig, const float* __restrict__ bsig,
                             float* __restrict__ out) {
    int idx = blockIdx.x * 256 + threadIdx.x;
    if (idx < 3600) {
        int b = idx / 225, p = idx % 225;
        float yv[13];
#pragma unroll
        for (int i = 0; i < 13; i++) yv[i] = leaky_f(g_y3[(p * 13 + i) * 16 + b]);
        float l[13];
        float m = -1e30f;
#pragma unroll
        for (int o = 0; o < 13; o++) {
            float s = bsm[o];
#pragma unroll
            for (int i = 0; i < 13; i++) s = fmaf(yv[i], wsm[i * 13 + o], s);
            l[o] = s;
            m = fmaxf(m, s);
        }
        float sum = 0.f;
#pragma unroll
        for (int o = 0; o < 13; o++) { l[o] = expf(l[o] - m); sum += l[o]; }
        float inv = 1.f / sum;
        float* dst = out + (size_t)(b * 225 + p) * 13;
#pragma unroll
        for (int o = 0; o < 13; o++) dst[o] = l[o] * inv;
    } else if (idx < 7200) {
        int j = idx - 3600;
        int b = j / 225, p = j % 225;
        float zv[4];
#pragma unroll
        for (int i = 0; i < 4; i++) zv[i] = leaky_f(g_z5[(p * 4 + i) * 16 + b]);
        float* dst = out + 46800 + (size_t)(b * 225 + p) * 4;
#pragma unroll
        for (int o = 0; o < 4; o++) {
            float s = bsig[o];
#pragma unroll
            for (int i = 0; i < 4; i++) s = fmaf(zv[i], wsig[i * 4 + o], s);
            dst[o] = 1.f / (1.f + expf(-s));
        }
    }
}

// ---------------- launch ----------------------------------------------------
extern "C" void kernel_launch(void* const* d_in, const int* in_sizes, int n_in,
                              void* d_out, int out_size) {
    const float* hidden  = (const float*)d_in[0];
    const float* conv1_w = (const float*)d_in[1];
    const float* conv1_b = (const float*)d_in[2];
    const float* conv2_w = (const float*)d_in[3];
    const float* conv2_b = (const float*)d_in[4];
    const float* w512    = (const float*)d_in[5];
    const float* b512    = (const float*)d_in[6];
    const float* w256a   = (const float*)d_in[7];
    const float* b256a   = (const float*)d_in[8];
    const float* wcls    = (const float*)d_in[9];
    const float* bcls    = (const float*)d_in[10];
    const float* wsm     = (const float*)d_in[11];
    const float* bsm     = (const float*)d_in[12];
    const float* w256b   = (const float*)d_in[13];
    const float* b256b   = (const float*)d_in[14];
    const float* w128a   = (const float*)d_in[15];
    const float* b128a   = (const float*)d_in[16];
    const float* w128b   = (const float*)d_in[17];
    const float* b128b   = (const float*)d_in[18];
    const float* w64     = (const float*)d_in[19];
    const float* b64     = (const float*)d_in[20];
    const float* wreg    = (const float*)d_in[21];
    const float* breg    = (const float*)d_in[22];
    const float* wsig    = (const float*)d_in[23];
    const float* bsig    = (const float*)d_in[24];
    float* out = (float*)d_out;

    float *ypre, *y2, *y3, *z4, *z5;
    cudaGetSymbolAddress((void**)&ypre, g_ypre);
    cudaGetSymbolAddress((void**)&y2, g_y2);
    cudaGetSymbolAddress((void**)&y3, g_y3);
    cudaGetSymbolAddress((void**)&z4, g_z4);
    cudaGetSymbolAddress((void**)&z5, g_z5);

    static bool attr_set = false;
    if (!attr_set) {
        cudaFuncSetAttribute(conv2_kernel, cudaFuncAttributeMaxDynamicSharedMemorySize, 54528);
        cudaFuncSetAttribute(fcbig_tf32_kernel, cudaFuncAttributeMaxDynamicSharedMemorySize, FC_SMEM_BYTES);
        attr_set = true;
    }

    prep_kernel<<<183, 256>>>(conv2_w, b512, b256b, bcls, b256a);
    conv1_kernel<<<dim3(P1H, BATCH), 256>>>(hidden, conv1_w, conv1_b);
    conv2_kernel<<<dim3(12, 24, BATCH), 256, 54528>>>(conv2_b);
    fcbig_tf32_kernel<<<NSLICES, 512, FC_SMEM_BYTES>>>(w512, w256b);

    splitfc_kernel<<<dim3(2, 4), 128>>>(ypre, w256a, y2, 256);
    splitfc_kernel<<<dim3(23, 2), 128>>>(y2, wcls, y3, 2925);
    zfused_kernel<<<1, 128>>>(w128a, b128a, w128b, b128b, w64, b64);
    smallfc_kernel<64><<<8, 128>>>(z4, wreg, breg, z5, 900);

    heads_kernel<<<29, 256>>>(wsm, bsm, wsig, bsig, out);
}

// round 9
// speedup vs baseline: 1.1680x; 1.0382x over previous
#include <cuda_runtime.h>
#include <cuda_bf16.h>
#include <mma.h>
#include <math.h>

using namespace nvcuda;

#define BATCH 16
#define P1H 97
#define P1W 383
#define C1 32
#define P2H 47
#define P2W 190
#define C2 64
#define FLAT 571520          // 47*190*64
#define KSLICE 640           // 893 * 640 = 571520 exactly
#define NSLICES 893
#define NCHUNK 80            // KSLICE / 8
#define FC_STAGES 3
#define FC_WLD 52                               // 48 cols + 4 pad floats per k-row
#define FC_STAGE_FLOATS (8 * FC_WLD)            // 416 floats per stage
#define FC_WARP_FLOATS (FC_STAGES * FC_STAGE_FLOATS)   // 1248
#define FC_SMEM_BYTES (16 * FC_WARP_FLOATS * 4)        // 79,872 B -> 2 CTAs/SM

// ---------------- scratch (device globals; allocations are forbidden) -------
__device__ __align__(128) __nv_bfloat16 g_x1b[(size_t)BATCH * P1H * P1W * C1]; // conv1 out bf16
__device__ __align__(16)  __nv_bfloat16 g_w2b[288 * 64];                       // conv2 weights bf16
__device__ __align__(16)  float g_x2[(size_t)BATCH * FLAT];                    // conv2 out [b][k]
__device__ float g_ypre[512 * 16];   // [n][b]
__device__ float g_zpre[256 * 16];
__device__ float g_y2[256 * 16];
__device__ float g_y3[2925 * 16];
__device__ float g_z4[64 * 16];
__device__ float g_z5[900 * 16];

__device__ __forceinline__ float leaky_f(float x) { return x >= 0.f ? x : 0.01f * x; }

// ---------------- prep: conv2 weight -> bf16 ; bias-init split-K accumulators
__global__ void prep_kernel(const float* __restrict__ w2,
                            const float* __restrict__ b512,
                            const float* __restrict__ b256b,
                            const float* __restrict__ bcls,
                            const float* __restrict__ b256a) {
    int i = blockIdx.x * 256 + threadIdx.x;
    if (i < 288 * 64) g_w2b[i] = __float2bfloat16(w2[i]);
    if (i < 512 * 16) g_ypre[i] = b512[i >> 4];
    if (i < 256 * 16) g_zpre[i] = b256b[i >> 4];
    if (i < 256 * 16) g_y2[i] = b256a[i >> 4];
    if (i < 2925 * 16) g_y3[i] = bcls[i >> 4];
}

// ---------------- conv1 (3x3, 1->32) + relu + maxpool2, fused, bf16 output --
__global__ void __launch_bounds__(256) conv1_kernel(const float* __restrict__ hidden,
                                                    const float* __restrict__ w1,
                                                    const float* __restrict__ b1) {
    __shared__ float ins[4 * 768];
    __shared__ float w1s[9 * 32];
    __shared__ float b1s[32];
    int b = blockIdx.y, ph = blockIdx.x;
    int tid = threadIdx.x;

    const float* src = hidden + ((size_t)b * 197 + 2 * ph) * 768;
    for (int i = tid; i < 4 * 768; i += 256) ins[i] = src[i];
    if (tid < 288) w1s[tid] = w1[tid];
    if (tid < 32) b1s[tid] = b1[tid];
    __syncthreads();

    int cg = tid >> 6;          // 0..3 (channel group of 8)
    int pwl = tid & 63;         // 0..63
    int c0 = cg * 8;

    float wv[9][8];
#pragma unroll
    for (int t = 0; t < 9; t++)
#pragma unroll
        for (int cc = 0; cc < 8; cc++) wv[t][cc] = w1s[t * 32 + c0 + cc];

    for (int it = 0; it < 6; it++) {
        int pw = it * 64 + pwl;
        if (pw >= 383) break;
        float in[4][4];
#pragma unroll
        for (int r = 0; r < 4; r++)
#pragma unroll
            for (int c = 0; c < 4; c++) in[r][c] = ins[r * 768 + 2 * pw + c];

        float acc[2][2][8];
#pragma unroll
        for (int i = 0; i < 2; i++)
#pragma unroll
            for (int j = 0; j < 2; j++)
#pragma unroll
                for (int cc = 0; cc < 8; cc++) acc[i][j][cc] = 0.f;

#pragma unroll
        for (int t = 0; t < 9; t++) {
            int kh = t / 3, kw = t % 3;
#pragma unroll
            for (int i = 0; i < 2; i++)
#pragma unroll
                for (int j = 0; j < 2; j++) {
                    float x = in[i + kh][j + kw];
#pragma unroll
                    for (int cc = 0; cc < 8; cc++)
                        acc[i][j][cc] = fmaf(x, wv[t][cc], acc[i][j][cc]);
                }
        }

        size_t o = (((size_t)b * P1H + ph) * P1W + pw) * C1 + c0;
        __nv_bfloat162* dst = reinterpret_cast<__nv_bfloat162*>(g_x1b + o);
#pragma unroll
        for (int t = 0; t < 4; t++) {
            int cc = 2 * t;
            float m0 = fmaxf(fmaxf(acc[0][0][cc],     acc[0][1][cc]),
                             fmaxf(acc[1][0][cc],     acc[1][1][cc]));
            float m1 = fmaxf(fmaxf(acc[0][0][cc + 1], acc[0][1][cc + 1]),
                             fmaxf(acc[1][0][cc + 1], acc[1][1][cc + 1]));
            dst[t] = __floats2bfloat162_rn(fmaxf(m0 + b1s[c0 + cc], 0.f),
                                           fmaxf(m1 + b1s[c0 + cc + 1], 0.f));
        }
    }
}

// ---------------- conv2 (3x3, 32->64) bf16 wmma implicit GEMM + relu + pool --
#define CV2_BPAD 72
__global__ void __launch_bounds__(256) conv2_kernel(const float* __restrict__ b2) {
    extern __shared__ __align__(16) __nv_bfloat16 smem_h[];
    __nv_bfloat16* x1s = smem_h;                 // 6*1088 halfs = 13056 B
    __nv_bfloat16* w2s = smem_h + 6 * 1088;      // 288*72 halfs = 41472 B

    int wt = blockIdx.x;        // 0..11
    int pb = blockIdx.y;        // 0..23
    int b = blockIdx.z;         // 0..15
    int tid = threadIdx.x;
    int h0 = 4 * pb;
    int w0 = wt * 32;

    // stage A: 6 rows x 136 uint4 (border-clamped; clamped data only feeds discarded outputs)
    for (int i = tid; i < 6 * 136; i += 256) {
        int r = i / 136, q = i - r * 136;
        int row = h0 + r; if (row > 96) row = 96;
        int col = w0 + (q >> 2); if (col > 382) col = 382;
        const uint4 v = *(const uint4*)(g_x1b + (((size_t)b * P1H + row) * P1W + col) * C1 + (q & 3) * 8);
        *(uint4*)(x1s + (size_t)r * 1088 + q * 8) = v;
    }
    // stage B with row padding 64->72: 288 rows x 8 uint4 (8 halves each)
    for (int i = tid; i < 2304; i += 256) {
        int k = i >> 3, n0 = (i & 7) * 8;
        uint4 v = *(const uint4*)(g_w2b + k * 64 + n0);
        *(uint4*)(w2s + k * CV2_BPAD + n0) = v;
    }
    __syncthreads();

    int wid = tid >> 5;
    int rloc = wid >> 1;            // conv-row offset 0..3
    int wOff = (wid & 1) * 16;      // col half

    wmma::fragment<wmma::matrix_a, 16, 16, 16, __nv_bfloat16, wmma::row_major> af;
    wmma::fragment<wmma::matrix_b, 16, 16, 16, __nv_bfloat16, wmma::row_major> bf;
    wmma::fragment<wmma::accumulator, 16, 16, 16, float> acc[4];
#pragma unroll
    for (int nf = 0; nf < 4; nf++) wmma::fill_fragment(acc[nf], 0.f);

#pragma unroll
    for (int kh = 0; kh < 3; kh++) {
        const __nv_bfloat16* ap = x1s + (rloc + kh) * 1088 + wOff * 32;
#pragma unroll
        for (int jc = 0; jc < 6; jc++) {
            wmma::load_matrix_sync(af, ap + jc * 16, 32);
            const __nv_bfloat16* bp = w2s + (kh * 96 + jc * 16) * CV2_BPAD;
#pragma unroll
            for (int nf = 0; nf < 4; nf++) {
                wmma::load_matrix_sync(bf, bp + nf * 16, CV2_BPAD);
                wmma::mma_sync(acc[nf], af, bf, acc[nf]);
            }
        }
    }

    __syncthreads();                 // B fully consumed -> reuse as C (fp32)
    float* cs = reinterpret_cast<float*>(w2s);   // 8 x 1024 floats = 32 KB
#pragma unroll
    for (int nf = 0; nf < 4; nf++)
        wmma::store_matrix_sync(cs + wid * 1024 + nf * 16, acc[nf], 64, wmma::mem_row_major);
    __syncthreads();

    // pooling epilogue: tid -> (pr 0..1, pj 0..15, 8 channels)
    int pr = tid >> 7;
    int pj = (tid >> 3) & 15;
    int c0 = (tid & 7) * 8;
    int ph2 = 2 * pb + pr;
    int pwg = wt * 16 + pj;
    if (ph2 < P2H && pwg < P2W) {
        float v[8];
#pragma unroll
        for (int cc = 0; cc < 8; cc++) {
            int c = c0 + cc;
            float m = -1e30f;
#pragma unroll
            for (int i = 0; i < 2; i++)
#pragma unroll
                for (int j = 0; j < 2; j++) {
                    int rr = 2 * pr + i;
                    int jj = 2 * pj + j;
                    m = fmaxf(m, cs[(rr * 2 + (jj >> 4)) * 1024 + (jj & 15) * 64 + c]);
                }
            v[cc] = fmaxf(m + b2[c], 0.f);
        }
        size_t o = (size_t)b * FLAT + ((size_t)ph2 * P2W + pwg) * C2 + c0;
        float4 o0 = {v[0], v[1], v[2], v[3]};
        float4 o1 = {v[4], v[5], v[6], v[7]};
        *reinterpret_cast<float4*>(g_x2 + o) = o0;
        *reinterpret_cast<float4*>(g_x2 + o + 4) = o1;
    }
}

// ---------------- big FC via TF32 tensor cores, warp-private cp.async rings --
// D[16, 768] += x[16, K] @ (w512 | w256b), split-K over 893 slices.
// 512 thr / 16 warps, 2 CTAs/SM. Warp w owns cols [48w, 48w+48) in a private
// 3-stage ring (prefetch depth 2). A fragments load DIRECTLY from g_x2
// (row-major, ld=FLAT, m=batch) — each chunk's 512B is L1-shared by all warps.
// NO CTA barriers anywhere.
__global__ void __launch_bounds__(512, 2) fcbig_tf32_kernel(const float* __restrict__ w512,
                                                            const float* __restrict__ w256b) {
    extern __shared__ __align__(16) float ws[];  // [16 warps][3 stages][8][FC_WLD]

    int tid = threadIdx.x;
    int wid = tid >> 5;
    int lane = tid & 31;
    size_t k0 = (size_t)blockIdx.x * KSLICE;

    // per-thread cp.async precompute: 3 x 16B per chunk over [8 rows][12 float4]
    const float* gsrc[3];
    int gstep[3];
    unsigned soff[3];
#pragma unroll
    for (int i = 0; i < 3; i++) {
        int idx = lane + i * 32;              // 0..95
        int r = idx / 12;
        int c4 = idx - r * 12;
        int gcol = wid * 48 + c4 * 4;
        if (gcol < 512) { gsrc[i] = w512  + (k0 + r) * 512 + gcol;         gstep[i] = 8 * 512; }
        else            { gsrc[i] = w256b + (k0 + r) * 256 + (gcol - 512); gstep[i] = 8 * 256; }
        soff[i] = (unsigned)((r * FC_WLD + c4 * 4) * 4);
    }
    unsigned wbase = (unsigned)__cvta_generic_to_shared(ws) + wid * (FC_WARP_FLOATS * 4);

#define FC_ISSUE(c)                                                               \
    {                                                                             \
        unsigned sb = wbase + ((c) % FC_STAGES) * (FC_STAGE_FLOATS * 4);          \
        _Pragma("unroll")                                                         \
        for (int i = 0; i < 3; i++) {                                             \
            const float* g = gsrc[i] + (size_t)(c) * gstep[i];                    \
            asm volatile("cp.async.cg.shared.global [%0], [%1], 16;"              \
                         :: "r"(sb + soff[i]), "l"(g));                           \
        }                                                                         \
        asm volatile("cp.async.commit_group;");                                   \
    }

    FC_ISSUE(0); FC_ISSUE(1);

    wmma::fragment<wmma::matrix_a, 16, 16, 8, wmma::precision::tf32, wmma::row_major> af;
    wmma::fragment<wmma::matrix_b, 16, 16, 8, wmma::precision::tf32, wmma::row_major> bfr;
    wmma::fragment<wmma::accumulator, 16, 16, 8, float> acc[3];
#pragma unroll
    for (int t = 0; t < 3; t++) wmma::fill_fragment(acc[t], 0.f);

    const float* wsw = ws + wid * FC_WARP_FLOATS;
    const float* abase = g_x2 + k0;              // A[m][kk] = abase[m*FLAT + c*8 + kk]
    for (int c = 0; c < NCHUNK; c++) {
        asm volatile("cp.async.wait_group 1;");
        __syncwarp();                            // warp-local visibility of chunk c

        wmma::load_matrix_sync(af, abase + c * 8, FLAT);   // gmem, L1-shared
        const float* buf = wsw + (c % FC_STAGES) * FC_STAGE_FLOATS;
#pragma unroll
        for (int t = 0; t < 3; t++) {
            wmma::load_matrix_sync(bfr, buf + t * 16, FC_WLD);
            wmma::mma_sync(acc[t], af, bfr, acc[t]);
        }

        if (c + 2 < NCHUNK) FC_ISSUE(c + 2);
    }
    asm volatile("cp.async.wait_group 0;");
    __syncwarp();

    // epilogue (barrier-free): each warp reuses its own ring as the patch buffer
    float* patch = ws + wid * FC_WARP_FLOATS;    // 256 floats needed, 1248 available
#pragma unroll
    for (int t = 0; t < 3; t++) {
        wmma::store_matrix_sync(patch, acc[t], 16, wmma::mem_row_major);
        __syncwarp();
        int gcb = wid * 48 + t * 16;
#pragma unroll
        for (int u = 0; u < 8; u++) {
            int e = lane + u * 32;
            int m = e >> 4, n = e & 15;
            int gcol = gcb + n;
            float val = patch[e];
            float* dst = (gcol < 512) ? (g_ypre + gcol * 16 + m)
                                      : (g_zpre + (gcol - 512) * 16 + m);
            atomicAdd(dst, val);
        }
        __syncwarp();
    }
#undef FC_ISSUE
}

// ---------------- small FC: outPre[n2][b] = bias[n2] + sum_k leaky(inPre[k][b]) w[k][n2]
template <int K>
__global__ void __launch_bounds__(128) smallfc_kernel(const float* __restrict__ inPre,
                                                      const float* __restrict__ w,
                                                      const float* __restrict__ bias,
                                                      float* __restrict__ outPre,
                                                      int N2) {
    __shared__ float xs[K * 16];
    int tid = threadIdx.x;
    for (int idx = tid; idx < K * 16; idx += 128) xs[idx] = leaky_f(inPre[idx]);
    __syncthreads();

    int n2 = blockIdx.x * 128 + tid;
    if (n2 < N2) {
        float acc[16];
#pragma unroll
        for (int b = 0; b < 16; b++) acc[b] = 0.f;
#pragma unroll 8
        for (int k = 0; k < K; k++) {
            float wv = __ldg(w + (size_t)k * N2 + n2);
#pragma unroll
            for (int b = 0; b < 16; b++) acc[b] = fmaf(wv, xs[k * 16 + b], acc[b]);
        }
        float bb = bias[n2];
#pragma unroll
        for (int b = 0; b < 16; b++) outPre[n2 * 16 + b] = acc[b] + bb;
    }
}

// ---------------- split-K small FC (128-row K slices), out pre-initialized with bias
__global__ void __launch_bounds__(128) splitfc_kernel(const float* __restrict__ inPre,
                                                      const float* __restrict__ w,
                                                      float* __restrict__ outAcc,
                                                      int N2) {
    __shared__ float xs[128 * 16];
    int tid = threadIdx.x;
    int kh = blockIdx.y;                    // k in [kh*128, kh*128+128)
    const float* ip = inPre + kh * 128 * 16;
    for (int idx = tid; idx < 128 * 16; idx += 128) xs[idx] = leaky_f(ip[idx]);
    __syncthreads();

    int n2 = blockIdx.x * 128 + tid;
    if (n2 < N2) {
        float acc[16];
#pragma unroll
        for (int b = 0; b < 16; b++) acc[b] = 0.f;
        const float* wp = w + (size_t)kh * 128 * N2 + n2;
#pragma unroll 8
        for (int k = 0; k < 128; k++) {
            float wv = __ldg(wp + (size_t)k * N2);
#pragma unroll
            for (int b = 0; b < 16; b++) acc[b] = fmaf(wv, xs[k * 16 + b], acc[b]);
        }
#pragma unroll
        for (int b = 0; b < 16; b++) atomicAdd(outAcc + n2 * 16 + b, acc[b]);
    }
}

// ---------------- fused z-chain: 256 ->128 ->128 ->64, one CTA ---------------
__global__ void __launch_bounds__(128) zfused_kernel(const float* __restrict__ w128a,
                                                     const float* __restrict__ b128a,
                                                     const float* __restrict__ w128b,
                                                     const float* __restrict__ b128b,
                                                     const float* __restrict__ w64,
                                                     const float* __restrict__ b64) {
    __shared__ float xa[256 * 16];
    __shared__ float xb[128 * 16];
    int tid = threadIdx.x;
    for (int idx = tid; idx < 256 * 16; idx += 128) xa[idx] = leaky_f(g_zpre[idx]);
    __syncthreads();

    {
        float acc[16];
#pragma unroll
        for (int b = 0; b < 16; b++) acc[b] = 0.f;
#pragma unroll 8
        for (int k = 0; k < 256; k++) {
            float wv = __ldg(w128a + (size_t)k * 128 + tid);
#pragma unroll
            for (int b = 0; b < 16; b++) acc[b] = fmaf(wv, xa[k * 16 + b], acc[b]);
        }
        float bb = b128a[tid];
#pragma unroll
        for (int b = 0; b < 16; b++) xb[tid * 16 + b] = leaky_f(acc[b] + bb);
    }
    __syncthreads();

    {
        float acc[16];
#pragma unroll
        for (int b = 0; b < 16; b++) acc[b] = 0.f;
#pragma unroll 8
        for (int k = 0; k < 128; k++) {
            float wv = __ldg(w128b + (size_t)k * 128 + tid);
#pragma unroll
            for (int b = 0; b < 16; b++) acc[b] = fmaf(wv, xb[k * 16 + b], acc[b]);
        }
        float bb = b128b[tid];
#pragma unroll
        for (int b = 0; b < 16; b++) xa[tid * 16 + b] = leaky_f(acc[b] + bb);
    }
    __syncthreads();

    if (tid < 64) {
        float acc[16];
#pragma unroll
        for (int b = 0; b < 16; b++) acc[b] = 0.f;
#pragma unroll 8
        for (int k = 0; k < 128; k++) {
            float wv = __ldg(w64 + (size_t)k * 64 + tid);
#pragma unroll
            for (int b = 0; b < 16; b++) acc[b] = fmaf(wv, xa[k * 16 + b], acc[b]);
        }
        float bb = b64[tid];
#pragma unroll
        for (int b = 0; b < 16; b++) g_z4[tid * 16 + b] = acc[b] + bb;
    }
}

// ---------------- heads: softmax(leaky(y3)@wsm+bsm), sigmoid(leaky(z5)@wsig+bsig)
__global__ void heads_kernel(const float* __restrict__ wsm, const float* __restrict__ bsm,
                             const float* __restrict__ wsig, const float* __restrict__ bsig,
                             float* __restrict__ out) {
    int idx = blockIdx.x * 256 + threadIdx.x;
    if (idx < 3600) {
        int b = idx / 225, p = idx % 225;
        float yv[13];
#pragma unroll
        for (int i = 0; i < 13; i++) yv[i] = leaky_f(g_y3[(p * 13 + i) * 16 + b]);
        float l[13];
        float m = -1e30f;
#pragma unroll
        for (int o = 0; o < 13; o++) {
            float s = bsm[o];
#pragma unroll
            for (int i = 0; i < 13; i++) s = fmaf(yv[i], wsm[i * 13 + o], s);
            l[o] = s;
            m = fmaxf(m, s);
        }
        float sum = 0.f;
#pragma unroll
        for (int o = 0; o < 13; o++) { l[o] = expf(l[o] - m); sum += l[o]; }
        float inv = 1.f / sum;
        float* dst = out + (size_t)(b * 225 + p) * 13;
#pragma unroll
        for (int o = 0; o < 13; o++) dst[o] = l[o] * inv;
    } else if (idx < 7200) {
        int j = idx - 3600;
        int b = j / 225, p = j % 225;
        float zv[4];
#pragma unroll
        for (int i = 0; i < 4; i++) zv[i] = leaky_f(g_z5[(p * 4 + i) * 16 + b]);
        float* dst = out + 46800 + (size_t)(b * 225 + p) * 4;
#pragma unroll
        for (int o = 0; o < 4; o++) {
            float s = bsig[o];
#pragma unroll
            for (int i = 0; i < 4; i++) s = fmaf(zv[i], wsig[i * 4 + o], s);
            dst[o] = 1.f / (1.f + expf(-s));
        }
    }
}

// ---------------- launch ----------------------------------------------------
extern "C" void kernel_launch(void* const* d_in, const int* in_sizes, int n_in,
                              void* d_out, int out_size) {
    const float* hidden  = (const float*)d_in[0];
    const float* conv1_w = (const float*)d_in[1];
    const float* conv1_b = (const float*)d_in[2];
    const float* conv2_w = (const float*)d_in[3];
    const float* conv2_b = (const float*)d_in[4];
    const float* w512    = (const float*)d_in[5];
    const float* b512    = (const float*)d_in[6];
    const float* w256a   = (const float*)d_in[7];
    const float* b256a   = (const float*)d_in[8];
    const float* wcls    = (const float*)d_in[9];
    const float* bcls    = (const float*)d_in[10];
    const float* wsm     = (const float*)d_in[11];
    const float* bsm     = (const float*)d_in[12];
    const float* w256b   = (const float*)d_in[13];
    const float* b256b   = (const float*)d_in[14];
    const float* w128a   = (const float*)d_in[15];
    const float* b128a   = (const float*)d_in[16];
    const float* w128b   = (const float*)d_in[17];
    const float* b128b   = (const float*)d_in[18];
    const float* w64     = (const float*)d_in[19];
    const float* b64     = (const float*)d_in[20];
    const float* wreg    = (const float*)d_in[21];
    const float* breg    = (const float*)d_in[22];
    const float* wsig    = (const float*)d_in[23];
    const float* bsig    = (const float*)d_in[24];
    float* out = (float*)d_out;

    float *ypre, *y2, *y3, *z4, *z5;
    cudaGetSymbolAddress((void**)&ypre, g_ypre);
    cudaGetSymbolAddress((void**)&y2, g_y2);
    cudaGetSymbolAddress((void**)&y3, g_y3);
    cudaGetSymbolAddress((void**)&z4, g_z4);
    cudaGetSymbolAddress((void**)&z5, g_z5);

    static bool attr_set = false;
    if (!attr_set) {
        cudaFuncSetAttribute(conv2_kernel, cudaFuncAttributeMaxDynamicSharedMemorySize, 54528);
        cudaFuncSetAttribute(fcbig_tf32_kernel, cudaFuncAttributeMaxDynamicSharedMemorySize, FC_SMEM_BYTES);
        attr_set = true;
    }

    prep_kernel<<<183, 256>>>(conv2_w, b512, b256b, bcls, b256a);
    conv1_kernel<<<dim3(P1H, BATCH), 256>>>(hidden, conv1_w, conv1_b);
    conv2_kernel<<<dim3(12, 24, BATCH), 256, 54528>>>(conv2_b);
    fcbig_tf32_kernel<<<NSLICES, 512, FC_SMEM_BYTES>>>(w512, w256b);

    splitfc_kernel<<<dim3(2, 4), 128>>>(ypre, w256a, y2, 256);
    splitfc_kernel<<<dim3(23, 2), 128>>>(y2, wcls, y3, 2925);
    zfused_kernel<<<1, 128>>>(w128a, b128a, w128b, b128b, w64, b64);
    smallfc_kernel<64><<<8, 128>>>(z4, wreg, breg, z5, 900);

    heads_kernel<<<29, 256>>>(wsm, bsm, wsig, bsig, out);
}